// round 1
// baseline (speedup 1.0000x reference)
#include <cuda_runtime.h>
#include <cuda_bf16.h>

#define UNITS 512
#define VOCAB 32000
#define BATCH 128
#define SEQ   64
#define ROWS  (BATCH * SEQ)   // 8192

// ---------------- scratch (no allocations allowed) ----------------
__device__ float g_score[ROWS];
__device__ float g_alpha[ROWS];
__device__ float g_context[BATCH * UNITS];
__device__ float g_xc[BATCH * 2 * UNITS];
__device__ float g_gates[BATCH * 3 * UNITS];
__device__ float g_y[BATCH * UNITS];

// ---------------- helpers ----------------
__device__ __forceinline__ float sigmoidf_(float x) { return 1.0f / (1.0f + expf(-x)); }

// ---------------- K0: init score with vb ----------------
__global__ void init_score_kernel(const float* __restrict__ vb) {
    int i = blockIdx.x * blockDim.x + threadIdx.x;
    if (i < ROWS) g_score[i] = vb[0];
}

// ---------------- K1: fused attn@W0 -> tanh -> dot(vW) -> score ----------------
// A: [8192, 512] (attention_inputs), B: W0 [512, 512]
// BM=128 BN=128 BK=16, 256 threads, 8x8 per thread (strided layout, conflict-free)
__global__ __launch_bounds__(256) void attn_gemm_kernel(
    const float* __restrict__ A, const float* __restrict__ W0,
    const float* __restrict__ b0, const float* __restrict__ b1,
    const float* __restrict__ vW)
{
    __shared__ float As[16][128];
    __shared__ float Bs[16][128];
    __shared__ float rowsum[128];

    int tid = threadIdx.x;
    int tr = tid >> 4;      // 0..15
    int tc = tid & 15;      // 0..15
    int row0 = blockIdx.y * 128;
    int col0 = blockIdx.x * 128;

    float acc[8][8] = {};

    for (int k0 = 0; k0 < UNITS; k0 += 16) {
        #pragma unroll
        for (int i = 0; i < 8; i++) {
            int idx = tid + i * 256;
            int m = idx >> 4;
            int k = idx & 15;
            As[k][m] = A[(size_t)(row0 + m) * UNITS + k0 + k];
        }
        #pragma unroll
        for (int i = 0; i < 8; i++) {
            int idx = tid + i * 256;
            int k = idx >> 7;
            int n = idx & 127;
            Bs[k][n] = W0[(size_t)(k0 + k) * UNITS + col0 + n];
        }
        __syncthreads();
        #pragma unroll
        for (int kk = 0; kk < 16; kk++) {
            float ra[8], rb[8];
            #pragma unroll
            for (int i = 0; i < 8; i++) ra[i] = As[kk][tr + i * 16];
            #pragma unroll
            for (int j = 0; j < 8; j++) rb[j] = Bs[kk][tc + j * 16];
            #pragma unroll
            for (int i = 0; i < 8; i++)
                #pragma unroll
                for (int j = 0; j < 8; j++) acc[i][j] += ra[i] * rb[j];
        }
        __syncthreads();
    }

    if (tid < 128) rowsum[tid] = 0.0f;
    __syncthreads();

    #pragma unroll
    for (int i = 0; i < 8; i++) {
        float s = 0.0f;
        #pragma unroll
        for (int j = 0; j < 8; j++) {
            int c = col0 + tc + j * 16;
            float v = tanhf(acc[i][j] + b0[c] + b1[c]);
            s += v * vW[c];
        }
        atomicAdd(&rowsum[tr + i * 16], s);
    }
    __syncthreads();
    if (tid < 128) atomicAdd(&g_score[row0 + tid], rowsum[tid]);
}

// ---------------- K2: softmax over SEQ ----------------
__global__ void softmax_kernel(float* __restrict__ out_alpha) {
    __shared__ float sh[SEQ];
    int b = blockIdx.x, t = threadIdx.x;
    float v = g_score[b * SEQ + t];
    sh[t] = v;
    __syncthreads();
    for (int off = 32; off > 0; off >>= 1) {
        if (t < off) sh[t] = fmaxf(sh[t], sh[t + off]);
        __syncthreads();
    }
    float m = sh[0];
    __syncthreads();
    float e = expf(v - m);
    sh[t] = e;
    __syncthreads();
    for (int off = 32; off > 0; off >>= 1) {
        if (t < off) sh[t] += sh[t + off];
        __syncthreads();
    }
    float a = e / sh[0];
    g_alpha[b * SEQ + t] = a;
    out_alpha[b * SEQ + t] = a;
}

// ---------------- K3: context = sum_s attn[b,s,:] * alpha[b,s] ----------------
__global__ void context_kernel(const float* __restrict__ attn) {
    __shared__ float sa[SEQ];
    int b = blockIdx.x, u = threadIdx.x;
    if (u < SEQ) sa[u] = g_alpha[b * SEQ + u];
    __syncthreads();
    const float* base = attn + (size_t)b * SEQ * UNITS + u;
    float acc = 0.0f;
    #pragma unroll
    for (int s = 0; s < SEQ; s++) acc += base[(size_t)s * UNITS] * sa[s];
    g_context[b * UNITS + u] = acc;
}

// ---------------- K4: xc = concat(emb[inputs], context) ----------------
__global__ void xc_kernel(const int* __restrict__ inp, const float* __restrict__ emb) {
    int b = blockIdx.x, u = threadIdx.x;
    g_xc[b * 2 * UNITS + u]          = emb[(size_t)inp[b] * UNITS + u];
    g_xc[b * 2 * UNITS + UNITS + u]  = g_context[b * UNITS + u];
}

// ---------------- generic tiled SGEMM (row-major A[M,K] x B[K,N] + bias, ACT) ----------------
// ACT: 0 = none, 1 = relu. All dims must divide by block tiles (true for our shapes).
template<int BM, int BN, int BK, int TM, int TN, int ACT>
__global__ void sgemm_kernel(const float* __restrict__ A, const float* __restrict__ B,
                             const float* __restrict__ bias, float* __restrict__ C,
                             int M, int N, int K)
{
    constexpr int TCOLS = BN / TN;
    constexpr int TROWS = BM / TM;
    constexpr int NT = TROWS * TCOLS;
    __shared__ float As[BK][BM];
    __shared__ float Bs[BK][BN];

    int tid = threadIdx.x;
    int tr = tid / TCOLS;
    int tc = tid % TCOLS;
    int row0 = blockIdx.y * BM;
    int col0 = blockIdx.x * BN;

    float acc[TM][TN] = {};

    for (int k0 = 0; k0 < K; k0 += BK) {
        for (int idx = tid; idx < BM * BK; idx += NT) {
            int m = idx / BK, k = idx % BK;
            As[k][m] = A[(size_t)(row0 + m) * K + k0 + k];
        }
        for (int idx = tid; idx < BK * BN; idx += NT) {
            int k = idx / BN, n = idx % BN;
            Bs[k][n] = B[(size_t)(k0 + k) * N + col0 + n];
        }
        __syncthreads();
        #pragma unroll
        for (int kk = 0; kk < BK; kk++) {
            float ra[TM], rb[TN];
            #pragma unroll
            for (int i = 0; i < TM; i++) ra[i] = As[kk][tr + i * TROWS];
            #pragma unroll
            for (int j = 0; j < TN; j++) rb[j] = Bs[kk][tc + j * TCOLS];
            #pragma unroll
            for (int i = 0; i < TM; i++)
                #pragma unroll
                for (int j = 0; j < TN; j++) acc[i][j] += ra[i] * rb[j];
        }
        __syncthreads();
    }

    #pragma unroll
    for (int i = 0; i < TM; i++) {
        int r = row0 + tr + i * TROWS;
        #pragma unroll
        for (int j = 0; j < TN; j++) {
            int c = col0 + tc + j * TCOLS;
            float v = acc[i][j] + bias[c];
            if (ACT == 1) v = fmaxf(v, 0.0f);
            C[(size_t)r * N + c] = v;
        }
    }
}

// ---------------- K6: gates -> state (h = 0) ----------------
__global__ void gru_state_kernel(const float* __restrict__ gru_b, float* __restrict__ out_state) {
    int b = blockIdx.x, u = threadIdx.x;
    const float* g = g_gates + b * 3 * UNITS;
    const float* rb = gru_b + 3 * UNITS;  // gru_b[1]
    float z  = sigmoidf_(g[u]             + rb[u]);
    float r  = sigmoidf_(g[UNITS + u]     + rb[UNITS + u]);
    float hh = tanhf    (g[2 * UNITS + u] + r * rb[2 * UNITS + u]);
    out_state[b * UNITS + u] = (1.0f - z) * hh;
}

// ---------------- launch ----------------
extern "C" void kernel_launch(void* const* d_in, const int* in_sizes, int n_in,
                              void* d_out, int out_size) {
    const int*   inp    = (const int*)d_in[0];
    const float* attn   = (const float*)d_in[1];
    const float* W0     = (const float*)d_in[2];
    const float* b0     = (const float*)d_in[3];
    const float* b1     = (const float*)d_in[5];
    const float* vW     = (const float*)d_in[6];
    const float* vb     = (const float*)d_in[7];
    const float* emb    = (const float*)d_in[8];
    const float* gru_k  = (const float*)d_in[9];
    const float* gru_b  = (const float*)d_in[11];
    const float* dW     = (const float*)d_in[12];
    const float* db     = (const float*)d_in[13];
    const float* oW     = (const float*)d_in[14];
    const float* ob     = (const float*)d_in[15];

    float* out        = (float*)d_out;
    float* out_logits = out;
    float* out_state  = out + (size_t)BATCH * VOCAB;
    float* out_alpha  = out + (size_t)BATCH * VOCAB + (size_t)BATCH * UNITS;

    float *p_xc, *p_gates, *p_y;
    cudaGetSymbolAddress((void**)&p_xc,    g_xc);
    cudaGetSymbolAddress((void**)&p_gates, g_gates);
    cudaGetSymbolAddress((void**)&p_y,     g_y);

    // 1. attention
    init_score_kernel<<<ROWS / 256, 256>>>(vb);
    attn_gemm_kernel<<<dim3(UNITS / 128, ROWS / 128), 256>>>(attn, W0, b0, b1, vW);
    softmax_kernel<<<BATCH, SEQ>>>(out_alpha);
    context_kernel<<<BATCH, UNITS>>>(attn);

    // 2. GRU input path
    xc_kernel<<<BATCH, UNITS>>>(inp, emb);
    // gates = xc @ gru_k + gru_b[0]   (128 x 1536, K=1024)
    sgemm_kernel<32, 64, 32, 4, 4, 0><<<dim3((3 * UNITS) / 64, BATCH / 32), 128>>>(
        p_xc, gru_k, gru_b, p_gates, BATCH, 3 * UNITS, 2 * UNITS);
    gru_state_kernel<<<BATCH, UNITS>>>(gru_b, out_state);

    // 3. y = relu(state @ dW + db)    (128 x 512, K=512)
    sgemm_kernel<32, 64, 32, 4, 4, 1><<<dim3(UNITS / 64, BATCH / 32), 128>>>(
        out_state, dW, db, p_y, BATCH, UNITS, UNITS);

    // 4. logits = y @ oW + ob         (128 x 32000, K=512)
    sgemm_kernel<128, 128, 16, 8, 8, 0><<<dim3(VOCAB / 128, BATCH / 128), 256>>>(
        p_y, oW, ob, out_logits, BATCH, VOCAB, UNITS);
}

// round 3
// speedup vs baseline: 1.9781x; 1.9781x over previous
#include <cuda_runtime.h>
#include <cuda_bf16.h>
#include <cstdint>

#define UNITS 512
#define VOCAB 32000
#define BATCH 128
#define SEQ   64
#define ROWS  (BATCH * SEQ)   // 8192

// ---------------- scratch (no allocations allowed) ----------------
__device__ float g_score[ROWS];
__device__ float g_alpha[ROWS];
__device__ float g_context[BATCH * UNITS];
__device__ float g_xc[BATCH * 2 * UNITS];
__device__ float g_gates[BATCH * 3 * UNITS];
__device__ float g_y[BATCH * UNITS];

__device__ __forceinline__ float sigmoidf_(float x) { return 1.0f / (1.0f + expf(-x)); }

__device__ __forceinline__ uint32_t f2tf32(float x) {
    uint32_t u;
    asm("cvt.rna.tf32.f32 %0, %1;" : "=r"(u) : "f"(x));
    return u;
}

__device__ __forceinline__ uint4 cvt4(float4 v) {
    uint4 u;
    u.x = f2tf32(v.x); u.y = f2tf32(v.y); u.z = f2tf32(v.z); u.w = f2tf32(v.w);
    return u;
}

__device__ __forceinline__ void mma_tf32(float c[4], uint32_t a0, uint32_t a1,
                                         uint32_t a2, uint32_t a3,
                                         uint32_t b0, uint32_t b1) {
    asm volatile(
        "mma.sync.aligned.m16n8k8.row.col.f32.tf32.tf32.f32 "
        "{%0,%1,%2,%3}, {%4,%5,%6,%7}, {%8,%9}, {%0,%1,%2,%3};"
        : "+f"(c[0]), "+f"(c[1]), "+f"(c[2]), "+f"(c[3])
        : "r"(a0), "r"(a1), "r"(a2), "r"(a3), "r"(b0), "r"(b1));
}

// ---------------- K0: init score with vb ----------------
__global__ void init_score_kernel(const float* __restrict__ vb) {
    int i = blockIdx.x * blockDim.x + threadIdx.x;
    if (i < ROWS) g_score[i] = vb[0];
}

// =================================================================
// TF32 tensor-core GEMM, 128x128x16 tile, 256 threads (8 warps 2x4)
// EPI=0: C = A@B + bias (ACT=1 -> relu)
// EPI=1: attention epilogue: tanh(acc + b0 + b1) . vW  -> atomic g_score
// =================================================================
template<int EPI, int ACT>
__global__ __launch_bounds__(256) void tf32_gemm(
    const float* __restrict__ A, const float* __restrict__ B,
    const float* __restrict__ bias, float* __restrict__ C,
    int M, int N, int K,
    const float* __restrict__ b1v, const float* __restrict__ vW)
{
    __shared__ uint32_t As[2][128][20];   // [buf][m][k], pad 16->20
    __shared__ uint32_t Bs[2][16][132];   // [buf][k][n], pad 128->132
    __shared__ float rowsum[128];

    const int tid  = threadIdx.x;
    const int lane = tid & 31;
    const int warp = tid >> 5;
    const int wm = warp >> 2;          // 0..1
    const int wn = warp & 3;           // 0..3
    const int q = lane & 3, r = lane >> 2;

    const int row0 = blockIdx.y * 128;
    const int col0 = blockIdx.x * 128;

    // global load mapping: A tile 128x16 (512 float4), B tile 16x128 (512 float4)
    const int a_row = tid >> 2;        // 0..63
    const int a_kq  = tid & 3;         // float4 within row
    const int b_kr  = tid >> 5;        // 0..7
    const int b_n4  = tid & 31;        // float4 within row

    const float4* Ag0 = (const float4*)(A + (size_t)(row0 + a_row) * K) + a_kq;
    const float4* Ag1 = (const float4*)(A + (size_t)(row0 + a_row + 64) * K) + a_kq;
    const float4* Bg0 = (const float4*)(B + (size_t)b_kr * N + col0) + b_n4;
    const float4* Bg1 = (const float4*)(B + (size_t)(b_kr + 8) * N + col0) + b_n4;
    const size_t bstep = (size_t)4 * N;   // 16 rows of B in float4 units

    float c[4][4][4];
    #pragma unroll
    for (int i = 0; i < 4; i++)
        #pragma unroll
        for (int j = 0; j < 4; j++)
            #pragma unroll
            for (int k = 0; k < 4; k++) c[i][j][k] = 0.0f;

    const int nkt = K / 16;

    // prologue: stage 0
    {
        float4 va0 = Ag0[0], va1 = Ag1[0], vb0 = Bg0[0], vb1 = Bg1[0];
        *(uint4*)&As[0][a_row][a_kq * 4]      = cvt4(va0);
        *(uint4*)&As[0][a_row + 64][a_kq * 4] = cvt4(va1);
        *(uint4*)&Bs[0][b_kr][b_n4 * 4]       = cvt4(vb0);
        *(uint4*)&Bs[0][b_kr + 8][b_n4 * 4]   = cvt4(vb1);
    }
    __syncthreads();

    for (int kt = 0; kt < nkt; kt++) {
        const int buf = kt & 1;
        float4 va0, va1, vb0, vb1;
        if (kt + 1 < nkt) {
            va0 = Ag0[(kt + 1) * 4];
            va1 = Ag1[(kt + 1) * 4];
            vb0 = Bg0[(size_t)(kt + 1) * bstep];
            vb1 = Bg1[(size_t)(kt + 1) * bstep];
        }

        #pragma unroll
        for (int kk = 0; kk < 2; kk++) {
            const int kb = kk * 8;
            uint32_t af[4][4], bf[4][2];
            #pragma unroll
            for (int i = 0; i < 4; i++) {
                int row = wm * 64 + i * 16 + r;
                af[i][0] = As[buf][row][kb + q];
                af[i][1] = As[buf][row + 8][kb + q];
                af[i][2] = As[buf][row][kb + q + 4];
                af[i][3] = As[buf][row + 8][kb + q + 4];
            }
            #pragma unroll
            for (int j = 0; j < 4; j++) {
                int col = wn * 32 + j * 8 + r;
                bf[j][0] = Bs[buf][kb + q][col];
                bf[j][1] = Bs[buf][kb + q + 4][col];
            }
            #pragma unroll
            for (int i = 0; i < 4; i++)
                #pragma unroll
                for (int j = 0; j < 4; j++)
                    mma_tf32(c[i][j], af[i][0], af[i][1], af[i][2], af[i][3],
                             bf[j][0], bf[j][1]);
        }

        if (kt + 1 < nkt) {
            __syncthreads();
            const int nb = buf ^ 1;
            *(uint4*)&As[nb][a_row][a_kq * 4]      = cvt4(va0);
            *(uint4*)&As[nb][a_row + 64][a_kq * 4] = cvt4(va1);
            *(uint4*)&Bs[nb][b_kr][b_n4 * 4]       = cvt4(vb0);
            *(uint4*)&Bs[nb][b_kr + 8][b_n4 * 4]   = cvt4(vb1);
            __syncthreads();
        }
    }

    if (EPI == 0) {
        #pragma unroll
        for (int i = 0; i < 4; i++) {
            int rr = row0 + wm * 64 + i * 16 + r;
            #pragma unroll
            for (int j = 0; j < 4; j++) {
                int cc = col0 + wn * 32 + j * 8 + 2 * q;
                float bia0 = bias[cc], bia1 = bias[cc + 1];
                float v00 = c[i][j][0] + bia0, v01 = c[i][j][1] + bia1;
                float v10 = c[i][j][2] + bia0, v11 = c[i][j][3] + bia1;
                if (ACT) {
                    v00 = fmaxf(v00, 0.f); v01 = fmaxf(v01, 0.f);
                    v10 = fmaxf(v10, 0.f); v11 = fmaxf(v11, 0.f);
                }
                float2 p0 = make_float2(v00, v01);
                float2 p1 = make_float2(v10, v11);
                *(float2*)&C[(size_t)rr * N + cc]       = p0;
                *(float2*)&C[(size_t)(rr + 8) * N + cc] = p1;
            }
        }
    } else {
        if (tid < 128) rowsum[tid] = 0.0f;
        __syncthreads();
        #pragma unroll
        for (int i = 0; i < 4; i++) {
            float s_lo = 0.0f, s_hi = 0.0f;
            #pragma unroll
            for (int j = 0; j < 4; j++) {
                int cc = col0 + wn * 32 + j * 8 + 2 * q;
                float w0 = vW[cc], w1 = vW[cc + 1];
                float bb0 = bias[cc] + b1v[cc];
                float bb1 = bias[cc + 1] + b1v[cc + 1];
                s_lo += tanhf(c[i][j][0] + bb0) * w0 + tanhf(c[i][j][1] + bb1) * w1;
                s_hi += tanhf(c[i][j][2] + bb0) * w0 + tanhf(c[i][j][3] + bb1) * w1;
            }
            s_lo += __shfl_xor_sync(0xffffffffu, s_lo, 1);
            s_lo += __shfl_xor_sync(0xffffffffu, s_lo, 2);
            s_hi += __shfl_xor_sync(0xffffffffu, s_hi, 1);
            s_hi += __shfl_xor_sync(0xffffffffu, s_hi, 2);
            if (q == 0) {
                atomicAdd(&rowsum[wm * 64 + i * 16 + r], s_lo);
                atomicAdd(&rowsum[wm * 64 + i * 16 + r + 8], s_hi);
            }
        }
        __syncthreads();
        if (tid < 128) atomicAdd(&g_score[row0 + tid], rowsum[tid]);
    }
}

// ---------------- K2: softmax over SEQ ----------------
__global__ void softmax_kernel(float* __restrict__ out_alpha) {
    __shared__ float sh[SEQ];
    int b = blockIdx.x, t = threadIdx.x;
    float v = g_score[b * SEQ + t];
    sh[t] = v;
    __syncthreads();
    for (int off = 32; off > 0; off >>= 1) {
        if (t < off) sh[t] = fmaxf(sh[t], sh[t + off]);
        __syncthreads();
    }
    float m = sh[0];
    __syncthreads();
    float e = expf(v - m);
    sh[t] = e;
    __syncthreads();
    for (int off = 32; off > 0; off >>= 1) {
        if (t < off) sh[t] += sh[t + off];
        __syncthreads();
    }
    float a = e / sh[0];
    g_alpha[b * SEQ + t] = a;
    out_alpha[b * SEQ + t] = a;
}

// ---------------- K3: context = sum_s attn[b,s,:] * alpha[b,s] ----------------
__global__ void context_kernel(const float* __restrict__ attn) {
    __shared__ float sa[SEQ];
    int b = blockIdx.x, t = threadIdx.x;     // block = 128 threads, one float4 each
    if (t < SEQ) sa[t] = g_alpha[b * SEQ + t];
    __syncthreads();
    const float4* base = (const float4*)(attn + (size_t)b * SEQ * UNITS) + t;
    float4 acc = make_float4(0.f, 0.f, 0.f, 0.f);
    #pragma unroll 8
    for (int s = 0; s < SEQ; s++) {
        float4 v = base[(size_t)s * (UNITS / 4)];
        float a = sa[s];
        acc.x += v.x * a; acc.y += v.y * a; acc.z += v.z * a; acc.w += v.w * a;
    }
    ((float4*)g_context)[b * (UNITS / 4) + t] = acc;
}

// ---------------- K4: xc = concat(emb[inputs], context) ----------------
__global__ void xc_kernel(const int* __restrict__ inp, const float* __restrict__ emb) {
    int b = blockIdx.x, u = threadIdx.x;
    g_xc[b * 2 * UNITS + u]         = emb[(size_t)inp[b] * UNITS + u];
    g_xc[b * 2 * UNITS + UNITS + u] = g_context[b * UNITS + u];
}

// ---------------- fp32 SGEMM for the small exact GEMMs ----------------
template<int BM, int BN, int BK, int TM, int TN, int ACT>
__global__ void sgemm_kernel(const float* __restrict__ A, const float* __restrict__ B,
                             const float* __restrict__ bias, float* __restrict__ C,
                             int M, int N, int K)
{
    constexpr int TCOLS = BN / TN;
    constexpr int TROWS = BM / TM;
    constexpr int NT = TROWS * TCOLS;
    __shared__ float As[BK][BM];
    __shared__ float Bs[BK][BN];

    int tid = threadIdx.x;
    int tr = tid / TCOLS;
    int tc = tid % TCOLS;
    int row0 = blockIdx.y * BM;
    int col0 = blockIdx.x * BN;

    float acc[TM][TN] = {};

    for (int k0 = 0; k0 < K; k0 += BK) {
        for (int idx = tid; idx < BM * BK; idx += NT) {
            int m = idx / BK, k = idx % BK;
            As[k][m] = A[(size_t)(row0 + m) * K + k0 + k];
        }
        for (int idx = tid; idx < BK * BN; idx += NT) {
            int k = idx / BN, n = idx % BN;
            Bs[k][n] = B[(size_t)(k0 + k) * N + col0 + n];
        }
        __syncthreads();
        #pragma unroll
        for (int kk = 0; kk < BK; kk++) {
            float ra[TM], rb[TN];
            #pragma unroll
            for (int i = 0; i < TM; i++) ra[i] = As[kk][tr + i * TROWS];
            #pragma unroll
            for (int j = 0; j < TN; j++) rb[j] = Bs[kk][tc + j * TCOLS];
            #pragma unroll
            for (int i = 0; i < TM; i++)
                #pragma unroll
                for (int j = 0; j < TN; j++) acc[i][j] += ra[i] * rb[j];
        }
        __syncthreads();
    }

    #pragma unroll
    for (int i = 0; i < TM; i++) {
        int rr = row0 + tr + i * TROWS;
        #pragma unroll
        for (int j = 0; j < TN; j++) {
            int cc = col0 + tc + j * TCOLS;
            float v = acc[i][j] + bias[cc];
            if (ACT == 1) v = fmaxf(v, 0.0f);
            C[(size_t)rr * N + cc] = v;
        }
    }
}

// ---------------- K6: gates -> state (h = 0) ----------------
__global__ void gru_state_kernel(const float* __restrict__ gru_b, float* __restrict__ out_state) {
    int b = blockIdx.x, u = threadIdx.x;
    const float* g = g_gates + b * 3 * UNITS;
    const float* rb = gru_b + 3 * UNITS;  // gru_b[1]
    float z  = sigmoidf_(g[u]             + rb[u]);
    float r  = sigmoidf_(g[UNITS + u]     + rb[UNITS + u]);
    float hh = tanhf    (g[2 * UNITS + u] + r * rb[2 * UNITS + u]);
    out_state[b * UNITS + u] = (1.0f - z) * hh;
}

// ---------------- launch ----------------
extern "C" void kernel_launch(void* const* d_in, const int* in_sizes, int n_in,
                              void* d_out, int out_size) {
    const int*   inp    = (const int*)d_in[0];
    const float* attn   = (const float*)d_in[1];
    const float* W0     = (const float*)d_in[2];
    const float* b0     = (const float*)d_in[3];
    const float* b1     = (const float*)d_in[5];
    const float* vW     = (const float*)d_in[6];
    const float* vb     = (const float*)d_in[7];
    const float* emb    = (const float*)d_in[8];
    const float* gru_k  = (const float*)d_in[9];
    const float* gru_b  = (const float*)d_in[11];
    const float* dW     = (const float*)d_in[12];
    const float* db     = (const float*)d_in[13];
    const float* oW     = (const float*)d_in[14];
    const float* ob     = (const float*)d_in[15];

    float* out        = (float*)d_out;
    float* out_logits = out;
    float* out_state  = out + (size_t)BATCH * VOCAB;
    float* out_alpha  = out + (size_t)BATCH * VOCAB + (size_t)BATCH * UNITS;

    float *p_xc, *p_gates, *p_y;
    cudaGetSymbolAddress((void**)&p_xc,    g_xc);
    cudaGetSymbolAddress((void**)&p_gates, g_gates);
    cudaGetSymbolAddress((void**)&p_y,     g_y);

    // 1. attention: score = tanh(attn@W0 + b0 + b1) . vW + vb   (tf32 tensor cores)
    init_score_kernel<<<ROWS / 256, 256>>>(vb);
    tf32_gemm<1, 0><<<dim3(UNITS / 128, ROWS / 128), 256>>>(
        attn, W0, b0, nullptr, ROWS, UNITS, UNITS, b1, vW);
    softmax_kernel<<<BATCH, SEQ>>>(out_alpha);
    context_kernel<<<BATCH, 128>>>(attn);

    // 2. GRU input path (exact fp32)
    xc_kernel<<<BATCH, UNITS>>>(inp, emb);
    sgemm_kernel<32, 32, 32, 2, 2, 0><<<dim3((3 * UNITS) / 32, BATCH / 32), 256>>>(
        p_xc, gru_k, gru_b, p_gates, BATCH, 3 * UNITS, 2 * UNITS);
    gru_state_kernel<<<BATCH, UNITS>>>(gru_b, out_state);

    // 3. y = relu(state @ dW + db) (exact fp32)
    sgemm_kernel<32, 32, 32, 2, 2, 1><<<dim3(UNITS / 32, BATCH / 32), 256>>>(
        out_state, dW, db, p_y, BATCH, UNITS, UNITS);

    // 4. logits = y @ oW + ob (tf32 tensor cores)
    tf32_gemm<0, 0><<<dim3(VOCAB / 128, BATCH / 128), 256>>>(
        p_y, oW, ob, out_logits, BATCH, VOCAB, UNITS, nullptr, nullptr);
}